// round 14
// baseline (speedup 1.0000x reference)
#include <cuda_runtime.h>
#include <cuda_fp16.h>
#include <math.h>
#include <stdint.h>

#define B_    4
#define L_    4096
#define D_    1024
#define DFF_  4096
#define KCAP_ 2048
#define UNSEL_ 2048

// ------------------------- scratch globals -------------------------
__device__ float g_scores[B_ * L_];
__device__ int   g_selidx[B_ * KCAP_];
__device__ int   g_unselidx[B_ * UNSEL_];

__device__ __align__(16) __half g_xg16[(size_t)B_ * KCAP_ * D_];
__device__ __align__(16) __half g_xu16[(size_t)B_ * UNSEL_ * D_];
__device__ __align__(16) __half g_wb16[(size_t)D_ * D_];
__device__ __align__(16) __half g_w116[(size_t)DFF_ * D_];
__device__ __align__(16) __half g_w216[(size_t)D_ * DFF_];
__device__ __align__(16) __half g_h16 [(size_t)B_ * KCAP_ * DFF_];

// ------------------------- helpers -------------------------
__device__ __forceinline__ uint32_t smem_u32(const void* p) {
    uint32_t a;
    asm("{ .reg .u64 t; cvta.to.shared.u64 t, %1; cvt.u32.u64 %0, t; }"
        : "=r"(a) : "l"(p));
    return a;
}
__device__ __forceinline__ void cp16(uint32_t dst, const void* src) {
    asm volatile("cp.async.cg.shared.global [%0], [%1], 16;" :: "r"(dst), "l"(src));
}
#define CP_COMMIT() asm volatile("cp.async.commit_group;" ::: "memory")
#define CP_WAIT2()  asm volatile("cp.async.wait_group 2;" ::: "memory")

__device__ __forceinline__ void ldx4(uint32_t r[4], uint32_t addr) {
    asm volatile("ldmatrix.sync.aligned.m8n8.x4.shared.b16 {%0,%1,%2,%3}, [%4];"
                 : "=r"(r[0]), "=r"(r[1]), "=r"(r[2]), "=r"(r[3]) : "r"(addr));
}
__device__ __forceinline__ void mma16816(float c[4], const uint32_t a[4], const uint32_t b[2]) {
    asm volatile(
        "mma.sync.aligned.m16n8k16.row.col.f32.f16.f16.f32 "
        "{%0,%1,%2,%3}, {%4,%5,%6,%7}, {%8,%9}, {%0,%1,%2,%3};"
        : "+f"(c[0]), "+f"(c[1]), "+f"(c[2]), "+f"(c[3])
        : "r"(a[0]), "r"(a[1]), "r"(a[2]), "r"(a[3]), "r"(b[0]), "r"(b[1]));
}
__device__ __forceinline__ float gelu_tanh(float v) {
    const float c = 0.7978845608028654f;
    float u = c * (v + 0.044715f * v * v * v);
    return 0.5f * v * (1.0f + tanhf(u));
}

// ------------------------- router scores -------------------------
__global__ void router_scores_kernel(const float* __restrict__ x,
                                     const float* __restrict__ wr) {
    int gwarp = (blockIdx.x * blockDim.x + threadIdx.x) >> 5;
    int lane  = threadIdx.x & 31;
    if (gwarp >= B_ * L_) return;
    const float4* xr = (const float4*)(x + (size_t)gwarp * D_);
    const float4* w4 = (const float4*)wr;
    float acc = 0.f;
#pragma unroll
    for (int i = 0; i < D_ / 4 / 32; i++) {
        float4 a = xr[lane + i * 32];
        float4 b = w4[lane + i * 32];
        acc += a.x * b.x + a.y * b.y + a.z * b.z + a.w * b.w;
    }
#pragma unroll
    for (int off = 16; off; off >>= 1)
        acc += __shfl_xor_sync(0xffffffffu, acc, off);
    if (lane == 0) g_scores[gwarp] = acc;
}

// ------------------- radix-select top-k + compact (1 block/batch) -------------------
__global__ void __launch_bounds__(1024) select_kernel() {
    __shared__ uint32_t keys[L_];
    __shared__ int hist[256];
    __shared__ int ws[32];
    __shared__ uint32_t sh_prefix;
    __shared__ int sh_rem;

    const int b = blockIdx.x;
    const int t = threadIdx.x;
    const int tok0 = t * 4;

    for (int i = t; i < L_; i += 1024) {
        uint32_t u = __float_as_uint(g_scores[b * L_ + i]);
        keys[i] = (u & 0x80000000u) ? ~u : (u | 0x80000000u);
    }
    if (t == 0) { sh_prefix = 0u; sh_rem = KCAP_; }
    __syncthreads();

    uint32_t k0 = keys[tok0], k1 = keys[tok0 + 1], k2 = keys[tok0 + 2], k3 = keys[tok0 + 3];
#pragma unroll
    for (int d = 3; d >= 0; d--) {
        if (t < 256) hist[t] = 0;
        __syncthreads();
        const uint32_t hm = (d == 3) ? 0u : (0xFFFFFFFFu << ((d + 1) * 8));
        const uint32_t pre = sh_prefix;
        const int sh = d * 8;
        if ((k0 & hm) == pre) atomicAdd(&hist[(k0 >> sh) & 255], 1);
        if ((k1 & hm) == pre) atomicAdd(&hist[(k1 >> sh) & 255], 1);
        if ((k2 & hm) == pre) atomicAdd(&hist[(k2 >> sh) & 255], 1);
        if ((k3 & hm) == pre) atomicAdd(&hist[(k3 >> sh) & 255], 1);
        __syncthreads();
        if (t == 0) {
            int rem = sh_rem, cum = 0, v = 255;
            for (; v > 0; v--) {
                int h = hist[v];
                if (cum + h >= rem) break;
                cum += h;
            }
            sh_prefix = pre | ((uint32_t)v << sh);
            sh_rem = rem - cum;
        }
        __syncthreads();
    }
    const uint32_t T = sh_prefix;
    const int need = sh_rem;

    const int lane = t & 31, w = t >> 5;

    int tie[4];
    tie[0] = (k0 == T); tie[1] = (k1 == T); tie[2] = (k2 == T); tie[3] = (k3 == T);
    int tc = tie[0] + tie[1] + tie[2] + tie[3];
    int tinc = tc;
#pragma unroll
    for (int off = 1; off < 32; off <<= 1) {
        int y = __shfl_up_sync(0xffffffffu, tinc, off);
        if (lane >= off) tinc += y;
    }
    if (lane == 31) ws[w] = tinc;
    __syncthreads();
    if (w == 0) {
        int v = ws[lane];
#pragma unroll
        for (int off = 1; off < 32; off <<= 1) {
            int y = __shfl_up_sync(0xffffffffu, v, off);
            if (lane >= off) v += y;
        }
        ws[lane] = v;
    }
    __syncthreads();
    int tie_pref = tinc - tc + (w ? ws[w - 1] : 0);
    __syncthreads();

    int f[4];
    uint32_t kk[4] = {k0, k1, k2, k3};
#pragma unroll
    for (int i = 0; i < 4; i++) {
        int sel = (kk[i] > T);
        if (tie[i]) { sel = (tie_pref < need); tie_pref++; }
        f[i] = sel;
    }

    int c = f[0] + f[1] + f[2] + f[3];
    int inc = c;
#pragma unroll
    for (int off = 1; off < 32; off <<= 1) {
        int y = __shfl_up_sync(0xffffffffu, inc, off);
        if (lane >= off) inc += y;
    }
    if (lane == 31) ws[w] = inc;
    __syncthreads();
    if (w == 0) {
        int v = ws[lane];
#pragma unroll
        for (int off = 1; off < 32; off <<= 1) {
            int y = __shfl_up_sync(0xffffffffu, v, off);
            if (lane >= off) v += y;
        }
        ws[lane] = v;
    }
    __syncthreads();
    int selp = inc - c + (w ? ws[w - 1] : 0);
    int unsp = tok0 - selp;
#pragma unroll
    for (int i = 0; i < 4; i++) {
        if (f[i]) g_selidx[b * KCAP_ + selp++] = tok0 + i;
        else      g_unselidx[b * UNSEL_ + unsp++] = tok0 + i;
    }
}

// ------------------------- merged prep: gathers + weight converts -------------------------
__device__ __forceinline__ void conv4(const float4* s, uint4* d) {
    float4 v0 = s[0], v1 = s[1], v2 = s[2], v3 = s[3];
    __half2 a0 = __floats2half2_rn(v0.x, v0.y), b0 = __floats2half2_rn(v0.z, v0.w);
    __half2 a1 = __floats2half2_rn(v1.x, v1.y), b1 = __floats2half2_rn(v1.z, v1.w);
    __half2 a2 = __floats2half2_rn(v2.x, v2.y), b2 = __floats2half2_rn(v2.z, v2.w);
    __half2 a3 = __floats2half2_rn(v3.x, v3.y), b3 = __floats2half2_rn(v3.z, v3.w);
    d[0] = make_uint4(*(uint32_t*)&a0, *(uint32_t*)&b0, *(uint32_t*)&a1, *(uint32_t*)&b1);
    d[1] = make_uint4(*(uint32_t*)&a2, *(uint32_t*)&b2, *(uint32_t*)&a3, *(uint32_t*)&b3);
}

__global__ void prep_all_kernel(const float* __restrict__ x,
                                const float* __restrict__ wb,
                                const float* __restrict__ w1,
                                const float* __restrict__ w2) {
    int t = blockIdx.x * blockDim.x + threadIdx.x;
    if (t < 1048576) {
        const int* idx;
        __half* dst;
        if (t < 524288) { idx = g_selidx;   dst = g_xg16; }
        else            { idx = g_unselidx; dst = g_xu16; t -= 524288; }
        int r  = t >> 6;
        int c0 = (t & 63) * 4;
        int srow = (r >> 11) * L_ + idx[r];
        conv4((const float4*)(x + (size_t)srow * D_) + c0,
              (uint4*)(dst + (size_t)r * D_) + (c0 >> 1));
    } else {
        t -= 1048576;
        const float* src;
        __half* dst;
        int off;
        if (t < 65536)       { src = wb; dst = g_wb16; off = t; }
        else if (t < 327680) { src = w1; dst = g_w116; off = t - 65536; }
        else                 { src = w2; dst = g_w216; off = t - 327680; }
        conv4((const float4*)src + off * 4, (uint4*)dst + off * 2);
    }
}

// ------------------------- HMMA GEMM: 2 chunks per barrier -----------------
// 128x128 CTA tile, 256 threads, 8 warps of 64x32. K-chunk 32, 6 stages,
// one __syncthreads per 2 chunks (wait_group 2, prefill 4).
#define BKC     32
#define TILEB   8192
#define STAGEB  (2 * TILEB)        // 16384
#define NSTAGE  6
#define SMEMB   (NSTAGE * STAGEB)  // 98304

#define SWZ(r, c) (((uint32_t)(r)) * 64u + ((((uint32_t)(c)) ^ ((((uint32_t)(r)) >> 1) & 3u)) << 4))

template <int FUSED>
__global__ void __launch_bounds__(256, 2) gemm_mma(float* __restrict__ outp) {
    constexpr int K  = FUSED ? D_ : DFF_;
    constexpr int NK = K / BKC;        // 32 or 128 (even)
    constexpr int NTILES = FUSED ? (512 + 2048) : 512;

    extern __shared__ char smem[];
    const uint32_t sbase = smem_u32(smem);

    const int tid  = threadIdx.x;
    const int lane = tid & 31;
    const int wid  = tid >> 5;

    const int pr = tid >> 1;
    const int pc = (tid & 1) * 2;
    const uint32_t d0 = SWZ(pr, pc);
    const uint32_t d1 = SWZ(pr, pc + 1);

    const uint32_t wrow0 = (wid & 1) * 64;
    const uint32_t wcol0 = (wid >> 1) * 32;
    const uint32_t aRow = wrow0 + (lane & 15);
    const uint32_t aK   = (lane >> 4);
    const uint32_t bRow = wcol0 + ((lane >> 4) << 3) + (lane & 7);
    const uint32_t bK   = (lane >> 3) & 1;

    uint32_t aBase[4], aSwz[4];
#pragma unroll
    for (int i = 0; i < 4; i++) {
        uint32_t r = aRow + i * 16;
        aBase[i] = r * 64u;
        aSwz[i]  = (r >> 1) & 3u;
    }
    uint32_t bBase[2], bSwz[2];
#pragma unroll
    for (int jp = 0; jp < 2; jp++) {
        uint32_t r = bRow + jp * 16;
        bBase[jp] = r * 64u;
        bSwz[jp]  = (r >> 1) & 3u;
    }

    const int t4  = lane >> 2;
    const int tm2 = (lane & 3) * 2;

    for (int tile = blockIdx.x; tile < NTILES; tile += gridDim.x) {
        int bm, bn;
        const __half* A;
        const __half* B;
        bool ffn1;
        if (FUSED) {
            ffn1 = (tile >= 512);
            if (ffn1) { int t = tile - 512; bm = t >> 5; bn = t & 31; A = g_xg16; B = g_w116; }
            else      { bm = tile >> 3; bn = tile & 7;   A = g_xu16; B = g_wb16; }
        } else {
            ffn1 = false;
            bm = tile >> 3; bn = tile & 7;
            A = g_h16; B = g_w216;
        }

        const __half* srcA = A + (size_t)(bm * 128 + pr) * K + pc * 8;
        const __half* srcB = B + (size_t)(bn * 128 + pr) * K + pc * 8;

#define LOAD_STAGE(ks, st) do {                                          \
        uint32_t b0 = sbase + (st) * STAGEB;                             \
        int ko = (ks) * BKC;                                             \
        cp16(b0 + d0,         srcA + ko);                                \
        cp16(b0 + d1,         srcA + ko + 8);                            \
        cp16(b0 + TILEB + d0, srcB + ko);                                \
        cp16(b0 + TILEB + d1, srcB + ko + 8);                            \
        CP_COMMIT();                                                     \
    } while (0)

// consume one 32-K chunk from stage base `base`
#define COMPUTE_CHUNK(base) do {                                         \
        _Pragma("unroll")                                                \
        for (int s = 0; s < 2; s++) {                                    \
            uint32_t a[4][4];                                            \
            uint32_t b[4][2];                                            \
            _Pragma("unroll")                                            \
            for (int i = 0; i < 4; i++) {                                \
                uint32_t c = 2 * s + aK;                                 \
                ldx4(a[i], (base) + aBase[i] + ((c ^ aSwz[i]) << 4));    \
            }                                                            \
            _Pragma("unroll")                                            \
            for (int jp = 0; jp < 2; jp++) {                             \
                uint32_t r[4];                                           \
                uint32_t c = 2 * s + bK;                                 \
                ldx4(r, (base) + TILEB + bBase[jp] + ((c ^ bSwz[jp]) << 4)); \
                b[2 * jp][0] = r[0]; b[2 * jp][1] = r[1];                \
                b[2 * jp + 1][0] = r[2]; b[2 * jp + 1][1] = r[3];        \
            }                                                            \
            _Pragma("unroll")                                            \
            for (int i = 0; i < 4; i++)                                  \
                _Pragma("unroll")                                        \
                for (int j = 0; j < 4; j++) mma16816(acc[i][j], a[i], b[j]); \
        }                                                                \
    } while (0)

        float acc[4][4][4];
#pragma unroll
        for (int i = 0; i < 4; i++)
#pragma unroll
            for (int j = 0; j < 4; j++)
#pragma unroll
                for (int q = 0; q < 4; q++) acc[i][j][q] = 0.f;

        // no warp may still read the previous tile's smem when we overwrite
        __syncthreads();

        LOAD_STAGE(0, 0);
        LOAD_STAGE(1, 1);
        LOAD_STAGE(2, 2);
        LOAD_STAGE(3, 3);

        int st = 0;
        for (int it = 0; it < NK / 2; it++) {
            const int ks = 2 * it;
            CP_WAIT2();
            __syncthreads();

            // issue loads for chunks ks+4, ks+5 into stages freed last iter
            if (ks + 4 < NK) {
                int s4 = st + 4; if (s4 >= NSTAGE) s4 -= NSTAGE;
                LOAD_STAGE(ks + 4, s4);
            } else {
                CP_COMMIT();
            }
            if (ks + 5 < NK) {
                int s5 = st + 5; if (s5 >= NSTAGE) s5 -= NSTAGE;
                LOAD_STAGE(ks + 5, s5);
            } else {
                CP_COMMIT();
            }

            const uint32_t base0 = sbase + st * STAGEB;
            int st1 = st + 1; if (st1 >= NSTAGE) st1 -= NSTAGE;
            const uint32_t base1 = sbase + st1 * STAGEB;
            COMPUTE_CHUNK(base0);
            COMPUTE_CHUNK(base1);

            st += 2; if (st >= NSTAGE) st -= NSTAGE;
        }

        // ---- epilogue ----
#pragma unroll
        for (int i = 0; i < 4; i++) {
            int r0 = bm * 128 + (int)wrow0 + i * 16 + t4;
            int r1 = r0 + 8;
            int or0, or1;
            if (FUSED) {
                if (ffn1) { or0 = r0; or1 = r1; }
                else { or0 = (r0 >> 11) * L_ + g_unselidx[r0]; or1 = (r1 >> 11) * L_ + g_unselidx[r1]; }
            } else {
                or0 = (r0 >> 11) * L_ + g_selidx[r0];
                or1 = (r1 >> 11) * L_ + g_selidx[r1];
            }
#pragma unroll
            for (int j = 0; j < 4; j++) {
                int col = bn * 128 + (int)wcol0 + j * 8 + tm2;
                if (FUSED && ffn1) {
                    __half2 p0 = __floats2half2_rn(gelu_tanh(acc[i][j][0]), gelu_tanh(acc[i][j][1]));
                    __half2 p1 = __floats2half2_rn(gelu_tanh(acc[i][j][2]), gelu_tanh(acc[i][j][3]));
                    *(uint32_t*)(g_h16 + (size_t)r0 * DFF_ + col) = *(uint32_t*)&p0;
                    *(uint32_t*)(g_h16 + (size_t)r1 * DFF_ + col) = *(uint32_t*)&p1;
                } else {
                    *(float2*)(outp + (size_t)or0 * D_ + col) = make_float2(acc[i][j][0], acc[i][j][1]);
                    *(float2*)(outp + (size_t)or1 * D_ + col) = make_float2(acc[i][j][2], acc[i][j][3]);
                }
            }
        }
#undef LOAD_STAGE
#undef COMPUTE_CHUNK
    }
}

// ------------------------- launch -------------------------
extern "C" void kernel_launch(void* const* d_in, const int* in_sizes, int n_in,
                              void* d_out, int out_size) {
    const float* x  = (const float*)d_in[0];
    const float* wr = (const float*)d_in[1];
    const float* wb = (const float*)d_in[2];
    const float* w1 = (const float*)d_in[3];
    const float* w2 = (const float*)d_in[4];
    float* out = (float*)d_out;

    cudaFuncSetAttribute(gemm_mma<1>, cudaFuncAttributeMaxDynamicSharedMemorySize, SMEMB);
    cudaFuncSetAttribute(gemm_mma<0>, cudaFuncAttributeMaxDynamicSharedMemorySize, SMEMB);

    router_scores_kernel<<<(B_ * L_) / 8, 256>>>(x, wr);              // 0
    select_kernel<<<B_, 1024>>>();                                    // 1
    prep_all_kernel<<<(1048576 + 589824) / 256, 256>>>(x, wb, w1, w2);// 2
    gemm_mma<1><<<296, 256, SMEMB>>>(out);                            // 3 (profiled)
    gemm_mma<0><<<296, 256, SMEMB>>>(out);                            // 4
}

// round 15
// speedup vs baseline: 1.0811x; 1.0811x over previous
#include <cuda_runtime.h>
#include <cuda_fp16.h>
#include <math.h>
#include <stdint.h>

#define B_    4
#define L_    4096
#define D_    1024
#define DFF_  4096
#define KCAP_ 2048
#define UNSEL_ 2048

// ------------------------- scratch globals -------------------------
__device__ float g_scores[B_ * L_];
__device__ int   g_selidx[B_ * KCAP_];
__device__ int   g_unselidx[B_ * UNSEL_];
__device__ int   g_rowdone[64];          // ffn1 row-completion counters

__device__ __align__(16) __half g_xg16[(size_t)B_ * KCAP_ * D_];
__device__ __align__(16) __half g_xu16[(size_t)B_ * UNSEL_ * D_];
__device__ __align__(16) __half g_wb16[(size_t)D_ * D_];
__device__ __align__(16) __half g_w116[(size_t)DFF_ * D_];
__device__ __align__(16) __half g_w216[(size_t)D_ * DFF_];
__device__ __align__(16) __half g_h16 [(size_t)B_ * KCAP_ * DFF_];

// ------------------------- helpers -------------------------
__device__ __forceinline__ uint32_t smem_u32(const void* p) {
    uint32_t a;
    asm("{ .reg .u64 t; cvta.to.shared.u64 t, %1; cvt.u32.u64 %0, t; }"
        : "=r"(a) : "l"(p));
    return a;
}
__device__ __forceinline__ void cp16(uint32_t dst, const void* src) {
    asm volatile("cp.async.cg.shared.global [%0], [%1], 16;" :: "r"(dst), "l"(src));
}
#define CP_COMMIT() asm volatile("cp.async.commit_group;" ::: "memory")
#define CP_WAIT3()  asm volatile("cp.async.wait_group 3;" ::: "memory")

__device__ __forceinline__ void ldx4(uint32_t r[4], uint32_t addr) {
    asm volatile("ldmatrix.sync.aligned.m8n8.x4.shared.b16 {%0,%1,%2,%3}, [%4];"
                 : "=r"(r[0]), "=r"(r[1]), "=r"(r[2]), "=r"(r[3]) : "r"(addr));
}
__device__ __forceinline__ void mma16816(float c[4], const uint32_t a[4], const uint32_t b[2]) {
    asm volatile(
        "mma.sync.aligned.m16n8k16.row.col.f32.f16.f16.f32 "
        "{%0,%1,%2,%3}, {%4,%5,%6,%7}, {%8,%9}, {%0,%1,%2,%3};"
        : "+f"(c[0]), "+f"(c[1]), "+f"(c[2]), "+f"(c[3])
        : "r"(a[0]), "r"(a[1]), "r"(a[2]), "r"(a[3]), "r"(b[0]), "r"(b[1]));
}
__device__ __forceinline__ float gelu_tanh(float v) {
    const float c = 0.7978845608028654f;
    float u = c * (v + 0.044715f * v * v * v);
    return 0.5f * v * (1.0f + tanhf(u));
}

// ------------------------- router scores -------------------------
__global__ void router_scores_kernel(const float* __restrict__ x,
                                     const float* __restrict__ wr) {
    int gwarp = (blockIdx.x * blockDim.x + threadIdx.x) >> 5;
    int lane  = threadIdx.x & 31;
    if (gwarp >= B_ * L_) return;
    const float4* xr = (const float4*)(x + (size_t)gwarp * D_);
    const float4* w4 = (const float4*)wr;
    float acc = 0.f;
#pragma unroll
    for (int i = 0; i < D_ / 4 / 32; i++) {
        float4 a = xr[lane + i * 32];
        float4 b = w4[lane + i * 32];
        acc += a.x * b.x + a.y * b.y + a.z * b.z + a.w * b.w;
    }
#pragma unroll
    for (int off = 16; off; off >>= 1)
        acc += __shfl_xor_sync(0xffffffffu, acc, off);
    if (lane == 0) g_scores[gwarp] = acc;
}

// ------------------- radix-select top-k + compact (1 block/batch) -------------------
__global__ void __launch_bounds__(1024) select_kernel() {
    __shared__ uint32_t keys[L_];
    __shared__ int hist[256];
    __shared__ int ws[32];
    __shared__ uint32_t sh_prefix;
    __shared__ int sh_rem;

    const int b = blockIdx.x;
    const int t = threadIdx.x;
    const int tok0 = t * 4;

    for (int i = t; i < L_; i += 1024) {
        uint32_t u = __float_as_uint(g_scores[b * L_ + i]);
        keys[i] = (u & 0x80000000u) ? ~u : (u | 0x80000000u);
    }
    if (t == 0) { sh_prefix = 0u; sh_rem = KCAP_; }
    __syncthreads();

    uint32_t k0 = keys[tok0], k1 = keys[tok0 + 1], k2 = keys[tok0 + 2], k3 = keys[tok0 + 3];
#pragma unroll
    for (int d = 3; d >= 0; d--) {
        if (t < 256) hist[t] = 0;
        __syncthreads();
        const uint32_t hm = (d == 3) ? 0u : (0xFFFFFFFFu << ((d + 1) * 8));
        const uint32_t pre = sh_prefix;
        const int sh = d * 8;
        if ((k0 & hm) == pre) atomicAdd(&hist[(k0 >> sh) & 255], 1);
        if ((k1 & hm) == pre) atomicAdd(&hist[(k1 >> sh) & 255], 1);
        if ((k2 & hm) == pre) atomicAdd(&hist[(k2 >> sh) & 255], 1);
        if ((k3 & hm) == pre) atomicAdd(&hist[(k3 >> sh) & 255], 1);
        __syncthreads();
        if (t == 0) {
            int rem = sh_rem, cum = 0, v = 255;
            for (; v > 0; v--) {
                int h = hist[v];
                if (cum + h >= rem) break;
                cum += h;
            }
            sh_prefix = pre | ((uint32_t)v << sh);
            sh_rem = rem - cum;
        }
        __syncthreads();
    }
    const uint32_t T = sh_prefix;
    const int need = sh_rem;

    const int lane = t & 31, w = t >> 5;

    int tie[4];
    tie[0] = (k0 == T); tie[1] = (k1 == T); tie[2] = (k2 == T); tie[3] = (k3 == T);
    int tc = tie[0] + tie[1] + tie[2] + tie[3];
    int tinc = tc;
#pragma unroll
    for (int off = 1; off < 32; off <<= 1) {
        int y = __shfl_up_sync(0xffffffffu, tinc, off);
        if (lane >= off) tinc += y;
    }
    if (lane == 31) ws[w] = tinc;
    __syncthreads();
    if (w == 0) {
        int v = ws[lane];
#pragma unroll
        for (int off = 1; off < 32; off <<= 1) {
            int y = __shfl_up_sync(0xffffffffu, v, off);
            if (lane >= off) v += y;
        }
        ws[lane] = v;
    }
    __syncthreads();
    int tie_pref = tinc - tc + (w ? ws[w - 1] : 0);
    __syncthreads();

    int f[4];
    uint32_t kk[4] = {k0, k1, k2, k3};
#pragma unroll
    for (int i = 0; i < 4; i++) {
        int sel = (kk[i] > T);
        if (tie[i]) { sel = (tie_pref < need); tie_pref++; }
        f[i] = sel;
    }

    int c = f[0] + f[1] + f[2] + f[3];
    int inc = c;
#pragma unroll
    for (int off = 1; off < 32; off <<= 1) {
        int y = __shfl_up_sync(0xffffffffu, inc, off);
        if (lane >= off) inc += y;
    }
    if (lane == 31) ws[w] = inc;
    __syncthreads();
    if (w == 0) {
        int v = ws[lane];
#pragma unroll
        for (int off = 1; off < 32; off <<= 1) {
            int y = __shfl_up_sync(0xffffffffu, v, off);
            if (lane >= off) v += y;
        }
        ws[lane] = v;
    }
    __syncthreads();
    int selp = inc - c + (w ? ws[w - 1] : 0);
    int unsp = tok0 - selp;
#pragma unroll
    for (int i = 0; i < 4; i++) {
        if (f[i]) g_selidx[b * KCAP_ + selp++] = tok0 + i;
        else      g_unselidx[b * UNSEL_ + unsp++] = tok0 + i;
    }
}

// ------------------------- merged prep: gathers + weight converts -------------------------
__device__ __forceinline__ void conv4(const float4* s, uint4* d) {
    float4 v0 = s[0], v1 = s[1], v2 = s[2], v3 = s[3];
    __half2 a0 = __floats2half2_rn(v0.x, v0.y), b0 = __floats2half2_rn(v0.z, v0.w);
    __half2 a1 = __floats2half2_rn(v1.x, v1.y), b1 = __floats2half2_rn(v1.z, v1.w);
    __half2 a2 = __floats2half2_rn(v2.x, v2.y), b2 = __floats2half2_rn(v2.z, v2.w);
    __half2 a3 = __floats2half2_rn(v3.x, v3.y), b3 = __floats2half2_rn(v3.z, v3.w);
    d[0] = make_uint4(*(uint32_t*)&a0, *(uint32_t*)&b0, *(uint32_t*)&a1, *(uint32_t*)&b1);
    d[1] = make_uint4(*(uint32_t*)&a2, *(uint32_t*)&b2, *(uint32_t*)&a3, *(uint32_t*)&b3);
}

__global__ void prep_all_kernel(const float* __restrict__ x,
                                const float* __restrict__ wb,
                                const float* __restrict__ w1,
                                const float* __restrict__ w2) {
    int t = blockIdx.x * blockDim.x + threadIdx.x;
    if (blockIdx.x == 0 && threadIdx.x < 64) g_rowdone[threadIdx.x] = 0;
    if (t < 1048576) {
        const int* idx;
        __half* dst;
        if (t < 524288) { idx = g_selidx;   dst = g_xg16; }
        else            { idx = g_unselidx; dst = g_xu16; t -= 524288; }
        int r  = t >> 6;
        int c0 = (t & 63) * 4;
        int srow = (r >> 11) * L_ + idx[r];
        conv4((const float4*)(x + (size_t)srow * D_) + c0,
              (uint4*)(dst + (size_t)r * D_) + (c0 >> 1));
    } else {
        t -= 1048576;
        const float* src;
        __half* dst;
        int off;
        if (t < 65536)       { src = wb; dst = g_wb16; off = t; }
        else if (t < 327680) { src = w1; dst = g_w116; off = t - 65536; }
        else                 { src = w2; dst = g_w216; off = t - 327680; }
        conv4((const float4*)src + off * 4, (uint4*)dst + off * 2);
    }
}

// ------------------------- merged HMMA GEMM (round-13 core + deps) -----------------
// tiles [0,512): bypass (K=1024, scatter unsel)
// tiles [512,2560): ffn1 (K=1024, gelu->h16, signal g_rowdone[bm])
// tiles [2560,3072): ffn2 (K=4096, wait g_rowdone[bm]==32, scatter sel)
#define BKC     32
#define TILEB   8192
#define STAGEB  (2 * TILEB)
#define NSTAGE  5
#define SMEMB   (NSTAGE * STAGEB)
#define NTILES  3072

#define SWZ(r, c) (((uint32_t)(r)) * 64u + ((((uint32_t)(c)) ^ ((((uint32_t)(r)) >> 1) & 3u)) << 4))

__global__ void __launch_bounds__(256, 2) gemm_all(float* __restrict__ outp) {
    extern __shared__ char smem[];
    const uint32_t sbase = smem_u32(smem);

    const int tid  = threadIdx.x;
    const int lane = tid & 31;
    const int wid  = tid >> 5;

    const int pr = tid >> 1;
    const int pc = (tid & 1) * 2;
    const uint32_t d0 = SWZ(pr, pc);
    const uint32_t d1 = SWZ(pr, pc + 1);

    const uint32_t wrow0 = (wid & 1) * 64;
    const uint32_t wcol0 = (wid >> 1) * 32;
    const uint32_t aRow = wrow0 + (lane & 15);
    const uint32_t aK   = (lane >> 4);
    const uint32_t bRow = wcol0 + ((lane >> 4) << 3) + (lane & 7);
    const uint32_t bK   = (lane >> 3) & 1;

    uint32_t aBase[4], aSwz[4];
#pragma unroll
    for (int i = 0; i < 4; i++) {
        uint32_t r = aRow + i * 16;
        aBase[i] = r * 64u;
        aSwz[i]  = (r >> 1) & 3u;
    }
    uint32_t bBase[2], bSwz[2];
#pragma unroll
    for (int jp = 0; jp < 2; jp++) {
        uint32_t r = bRow + jp * 16;
        bBase[jp] = r * 64u;
        bSwz[jp]  = (r >> 1) & 3u;
    }

    const int t4  = lane >> 2;
    const int tm2 = (lane & 3) * 2;

    for (int tile = blockIdx.x; tile < NTILES; tile += gridDim.x) {
        int bm, bn, K, kind;   // kind: 0 bypass, 1 ffn1, 2 ffn2
        const __half* A;
        const __half* B;
        if (tile < 512) {
            kind = 0; bm = tile >> 3; bn = tile & 7;
            A = g_xu16; B = g_wb16; K = D_;
        } else if (tile < 2560) {
            kind = 1; int t = tile - 512; bm = t >> 5; bn = t & 31;
            A = g_xg16; B = g_w116; K = D_;
        } else {
            kind = 2; int t = tile - 2560; bm = t >> 3; bn = t & 7;
            A = g_h16; B = g_w216; K = DFF_;
        }
        const int NK = K / BKC;

        // ffn2 dependency: wait until all 32 ffn1 tiles of row bm are done
        if (kind == 2) {
            if (tid == 0) {
                int v;
                do {
                    asm volatile("ld.global.acquire.gpu.b32 %0, [%1];"
                                 : "=r"(v) : "l"(&g_rowdone[bm]) : "memory");
                } while (v < 32);
                __threadfence();
            }
            // sync below (pre-prologue) orders all threads after the wait
        }

        const __half* srcA = A + (size_t)(bm * 128 + pr) * K + pc * 8;
        const __half* srcB = B + (size_t)(bn * 128 + pr) * K + pc * 8;

#define LOAD_STAGE(ks, st) do {                                          \
        uint32_t b0 = sbase + (st) * STAGEB;                             \
        int ko = (ks) * BKC;                                             \
        cp16(b0 + d0,         srcA + ko);                                \
        cp16(b0 + d1,         srcA + ko + 8);                            \
        cp16(b0 + TILEB + d0, srcB + ko);                                \
        cp16(b0 + TILEB + d1, srcB + ko + 8);                            \
        CP_COMMIT();                                                     \
    } while (0)

        float acc[4][4][4];
#pragma unroll
        for (int i = 0; i < 4; i++)
#pragma unroll
            for (int j = 0; j < 4; j++)
#pragma unroll
                for (int q = 0; q < 4; q++) acc[i][j][q] = 0.f;

        // orders: previous tile's smem reads done; ffn2 dependency wait done
        __syncthreads();

        LOAD_STAGE(0, 0);
        LOAD_STAGE(1, 1);
        LOAD_STAGE(2, 2);
        LOAD_STAGE(3, 3);

        int st = 0;
        for (int ks = 0; ks < NK; ks++) {
            CP_WAIT3();
            __syncthreads();

            if (ks + 4 < NK) {
                int st4 = st + 4; if (st4 >= NSTAGE) st4 -= NSTAGE;
                LOAD_STAGE(ks + 4, st4);
            } else {
                CP_COMMIT();
            }

            const uint32_t base = sbase + st * STAGEB;
#pragma unroll
            for (int s = 0; s < 2; s++) {
                uint32_t a[4][4];
                uint32_t b[4][2];
#pragma unroll
                for (int i = 0; i < 4; i++) {
                    uint32_t c = 2 * s + aK;
                    ldx4(a[i], base + aBase[i] + ((c ^ aSwz[i]) << 4));
                }
#pragma unroll
                for (int jp = 0; jp < 2; jp++) {
                    uint32_t r[4];
                    uint32_t c = 2 * s + bK;
                    ldx4(r, base + TILEB + bBase[jp] + ((c ^ bSwz[jp]) << 4));
                    b[2 * jp][0] = r[0]; b[2 * jp][1] = r[1];
                    b[2 * jp + 1][0] = r[2]; b[2 * jp + 1][1] = r[3];
                }
#pragma unroll
                for (int i = 0; i < 4; i++)
#pragma unroll
                    for (int j = 0; j < 4; j++) mma16816(acc[i][j], a[i], b[j]);
            }
            if (++st == NSTAGE) st = 0;
        }

        // ---- epilogue ----
#pragma unroll
        for (int i = 0; i < 4; i++) {
            int r0 = bm * 128 + (int)wrow0 + i * 16 + t4;
            int r1 = r0 + 8;
            int or0, or1;
            if (kind == 1)      { or0 = r0; or1 = r1; }
            else if (kind == 0) { or0 = (r0 >> 11) * L_ + g_unselidx[r0]; or1 = (r1 >> 11) * L_ + g_unselidx[r1]; }
            else                { or0 = (r0 >> 11) * L_ + g_selidx[r0];   or1 = (r1 >> 11) * L_ + g_selidx[r1];   }
#pragma unroll
            for (int j = 0; j < 4; j++) {
                int col = bn * 128 + (int)wcol0 + j * 8 + tm2;
                if (kind == 1) {
                    __half2 p0 = __floats2half2_rn(gelu_tanh(acc[i][j][0]), gelu_tanh(acc[i][j][1]));
                    __half2 p1 = __floats2half2_rn(gelu_tanh(acc[i][j][2]), gelu_tanh(acc[i][j][3]));
                    *(uint32_t*)(g_h16 + (size_t)r0 * DFF_ + col) = *(uint32_t*)&p0;
                    *(uint32_t*)(g_h16 + (size_t)r1 * DFF_ + col) = *(uint32_t*)&p1;
                } else {
                    *(float2*)(outp + (size_t)or0 * D_ + col) = make_float2(acc[i][j][0], acc[i][j][1]);
                    *(float2*)(outp + (size_t)or1 * D_ + col) = make_float2(acc[i][j][2], acc[i][j][3]);
                }
            }
        }

        // ffn1: signal row completion (store -> fence -> barrier -> atomic)
        if (kind == 1) {
            __threadfence();
            __syncthreads();
            if (tid == 0) atomicAdd(&g_rowdone[bm], 1);
        }
#undef LOAD_STAGE
    }
}

// ------------------------- launch -------------------------
extern "C" void kernel_launch(void* const* d_in, const int* in_sizes, int n_in,
                              void* d_out, int out_size) {
    const float* x  = (const float*)d_in[0];
    const float* wr = (const float*)d_in[1];
    const float* wb = (const float*)d_in[2];
    const float* w1 = (const float*)d_in[3];
    const float* w2 = (const float*)d_in[4];
    float* out = (float*)d_out;

    cudaFuncSetAttribute(gemm_all, cudaFuncAttributeMaxDynamicSharedMemorySize, SMEMB);

    router_scores_kernel<<<(B_ * L_) / 8, 256>>>(x, wr);              // 0
    select_kernel<<<B_, 1024>>>();                                    // 1
    prep_all_kernel<<<(1048576 + 589824) / 256, 256>>>(x, wb, w1, w2);// 2
    gemm_all<<<296, 256, SMEMB>>>(out);                               // 3 (profiled)
}